// round 13
// baseline (speedup 1.0000x reference)
#include <cuda_runtime.h>
#include <math.h>
#include <stdint.h>

#define B_ 8
#define S_ 1024
#define D_ 1024
#define H_ 16
#define KD 64
#define NEGINF (-1e9f)

// Scratch (allocation-free rule: __device__ globals)
static __device__ float g_q[B_ * S_ * H_ * KD];
static __device__ float g_k[B_ * S_ * H_ * KD];
static __device__ float g_v[B_ * S_ * H_ * KD];
static __device__ float g_ctx[B_ * S_ * H_ * KD];
static __device__ float g_maskf[B_ * S_];

// ---------------------------------------------------------------------------
static __device__ __forceinline__ uint32_t f2tf32(float f) {
    uint32_t u;
    asm("cvt.rna.tf32.f32 %0, %1;" : "=r"(u) : "f"(f));
    return u;
}

static __device__ __forceinline__ void mma_tf32(float* d,
                                                const uint32_t* a,
                                                const uint32_t* b) {
    asm volatile(
        "mma.sync.aligned.m16n8k8.row.col.f32.tf32.tf32.f32 "
        "{%0,%1,%2,%3}, {%4,%5,%6,%7}, {%8,%9}, {%0,%1,%2,%3};"
        : "+f"(d[0]), "+f"(d[1]), "+f"(d[2]), "+f"(d[3])
        : "r"(a[0]), "r"(a[1]), "r"(a[2]), "r"(a[3]),
          "r"(b[0]), "r"(b[1]));
}

// ---------------------------------------------------------------------------
// Mask dtype sniffing + normalization into g_maskf (1.0 / 0.0 per token).
// ---------------------------------------------------------------------------
__global__ void mask_norm_kernel(const unsigned char* __restrict__ m)
{
    __shared__ int mode;  // 1 = 4-byte words, 0 = bytes
    if (threadIdx.x == 0) {
        int any_ge2 = 0, any_off = 0;
        for (int i = 0; i < 512; i++) {
            unsigned char v = m[i];
            if (v >= 2) any_ge2 = 1;
            if ((i & 3) && v) any_off = 1;
        }
        mode = (any_ge2 || !any_off) ? 1 : 0;
    }
    __syncthreads();
    const int n = B_ * S_;
    if (mode) {
        const unsigned int* w = (const unsigned int*)m;
        for (int i = threadIdx.x; i < n; i += blockDim.x)
            g_maskf[i] = w[i] ? 1.f : 0.f;
    } else {
        for (int i = threadIdx.x; i < n; i += blockDim.x)
            g_maskf[i] = m[i] ? 1.f : 0.f;
    }
}

// ---------------------------------------------------------------------------
// tf32 mma.sync GEMM: C[M,N] = A[M,K] @ B[K,N] + bias[N]
// M=8192, N=K=1024. CTA 128x128, BK=32, 8 warps x (64x32) warp tiles.
// A kept [m][k]; B transposed into [n][k] during staging. cvt.rna at staging.
// ---------------------------------------------------------------------------
__global__ __launch_bounds__(256, 2)
void gemm_mma_kernel(const float* __restrict__ A,
                     const float* __restrict__ Bm,
                     const float* __restrict__ bias,
                     float* __restrict__ C)
{
    __shared__ float sA[128][36];
    __shared__ float sB[128][36];

    const int tid = threadIdx.x;
    const int wid = tid >> 5, lane = tid & 31;
    const int bm = blockIdx.y, bn = blockIdx.x;

    const int warp_m = (wid & 1) * 64;   // 0 / 64
    const int warp_n = (wid >> 1) * 32;  // 0 / 32 / 64 / 96
    const int gr = lane >> 2;            // 0..7
    const int tc = lane & 3;             // 0..3

    float acc[4][4][4];
#pragma unroll
    for (int mt = 0; mt < 4; mt++)
#pragma unroll
        for (int nt = 0; nt < 4; nt++)
#pragma unroll
            for (int r = 0; r < 4; r++) acc[mt][nt][r] = 0.f;

    const float* Ap = A + (size_t)(bm * 128) * 1024;
    const float* Bp = Bm + bn * 128;

    const int am = tid >> 3;         // 0..31 (A row within pass)
    const int ak = (tid & 7) * 4;    // 0..28
    const int nb = tid & 127;        // B column (n)
    const int kh = (tid >> 7) * 16;  // B k-half

    for (int k0 = 0; k0 < 1024; k0 += 32) {
        // Stage A [128m x 32k], coalesced 128B rows, cvt.rna to tf32
#pragma unroll
        for (int p = 0; p < 4; p++) {
            const int m = p * 32 + am;
            float4 v = *(const float4*)(Ap + (size_t)m * 1024 + k0 + ak);
            uint32_t* dst = (uint32_t*)&sA[m][ak];
            dst[0] = f2tf32(v.x);
            dst[1] = f2tf32(v.y);
            dst[2] = f2tf32(v.z);
            dst[3] = f2tf32(v.w);
        }
        // Stage B transposed -> sB[n][k]; scalar reads coalesced over n
#pragma unroll
        for (int q = 0; q < 4; q++) {
            const int kk = k0 + kh + q * 4;
            uint32_t* dst = (uint32_t*)&sB[nb][kh + q * 4];
            dst[0] = f2tf32(Bp[(size_t)(kk + 0) * 1024 + nb]);
            dst[1] = f2tf32(Bp[(size_t)(kk + 1) * 1024 + nb]);
            dst[2] = f2tf32(Bp[(size_t)(kk + 2) * 1024 + nb]);
            dst[3] = f2tf32(Bp[(size_t)(kk + 3) * 1024 + nb]);
        }
        __syncthreads();

#pragma unroll
        for (int ks = 0; ks < 4; ks++) {
            const int kq = ks * 8;
            uint32_t af[4][4], bf[4][2];
#pragma unroll
            for (int mt = 0; mt < 4; mt++) {
                const int r = warp_m + mt * 16 + gr;
                af[mt][0] = __float_as_uint(sA[r][kq + tc]);
                af[mt][1] = __float_as_uint(sA[r + 8][kq + tc]);
                af[mt][2] = __float_as_uint(sA[r][kq + tc + 4]);
                af[mt][3] = __float_as_uint(sA[r + 8][kq + tc + 4]);
            }
#pragma unroll
            for (int nt = 0; nt < 4; nt++) {
                const int n = warp_n + nt * 8 + gr;
                bf[nt][0] = __float_as_uint(sB[n][kq + tc]);
                bf[nt][1] = __float_as_uint(sB[n][kq + tc + 4]);
            }
#pragma unroll
            for (int mt = 0; mt < 4; mt++)
#pragma unroll
                for (int nt = 0; nt < 4; nt++)
                    mma_tf32(acc[mt][nt], af[mt], bf[nt]);
        }
        __syncthreads();
    }

    // Epilogue: c0:(g,2tc) c1:(g,2tc+1) c2:(g+8,2tc) c3:(g+8,2tc+1)
#pragma unroll
    for (int mt = 0; mt < 4; mt++) {
        const int row0 = bm * 128 + warp_m + mt * 16 + gr;
#pragma unroll
        for (int nt = 0; nt < 4; nt++) {
            const int col = bn * 128 + warp_n + nt * 8 + 2 * tc;
            const float b0 = bias[col], b1 = bias[col + 1];
            float* c0 = C + (size_t)row0 * 1024 + col;
            float* c1 = C + (size_t)(row0 + 8) * 1024 + col;
            c0[0] = acc[mt][nt][0] + b0;
            c0[1] = acc[mt][nt][1] + b1;
            c1[0] = acc[mt][nt][2] + b0;
            c1[1] = acc[mt][nt][3] + b1;
        }
    }
}

// ---------------------------------------------------------------------------
// Flash attention over one (b, h, 128-query tile). Key tiles of 64. (fp32)
// ---------------------------------------------------------------------------
__global__ __launch_bounds__(256, 1)
void attn_kernel()
{
    extern __shared__ float sm[];
    float* Qs  = sm;                 // [128][65]
    float* Ks  = Qs + 128 * 65;      // [64][65]
    float* Vs  = Ks + 64 * 65;       // [64][64]
    float* Ps  = Vs + 64 * 64;       // [128][65]
    float* mqs = Ps + 128 * 65;      // [128]
    float* mks = mqs + 128;          // [64]

    const int tid = threadIdx.x;
    const int ty = tid >> 4, tx = tid & 15;
    const int qt = blockIdx.x;
    const int h  = blockIdx.y;
    const int b  = blockIdx.z;
    const int q0 = qt * 128;

    for (int t = tid; t < 128 * 16; t += 256) {
        int r = t >> 4, c4 = (t & 15) << 2;
        float4 v4 = *(const float4*)(g_q +
            ((size_t)((b * S_ + q0 + r) * H_ + h)) * KD + c4);
        float* dst = Qs + r * 65 + c4;
        dst[0] = v4.x; dst[1] = v4.y; dst[2] = v4.z; dst[3] = v4.w;
    }
    if (tid < 128) mqs[tid] = g_maskf[b * S_ + q0 + tid];

    float m_i[8], l_i[8], O[8][4];
#pragma unroll
    for (int i = 0; i < 8; i++) {
        m_i[i] = -INFINITY;
        l_i[i] = 0.f;
#pragma unroll
        for (int j = 0; j < 4; j++) O[i][j] = 0.f;
    }

    for (int jt = 0; jt < 16; jt++) {
        const int k0 = jt * 64;
        __syncthreads();
        for (int t = tid; t < 64 * 16; t += 256) {
            int r = t >> 4, c4 = (t & 15) << 2;
            size_t base = ((size_t)((b * S_ + k0 + r) * H_ + h)) * KD + c4;
            float4 kv = *(const float4*)(g_k + base);
            float* kd = Ks + r * 65 + c4;
            kd[0] = kv.x; kd[1] = kv.y; kd[2] = kv.z; kd[3] = kv.w;
            *(float4*)(Vs + r * 64 + c4) = *(const float4*)(g_v + base);
        }
        if (tid < 64) mks[tid] = g_maskf[b * S_ + k0 + tid];
        __syncthreads();

        float sc[8][4];
#pragma unroll
        for (int i = 0; i < 8; i++)
#pragma unroll
            for (int j = 0; j < 4; j++) sc[i][j] = 0.f;

#pragma unroll 8
        for (int kk = 0; kk < 64; kk++) {
            float af[8], bf[4];
#pragma unroll
            for (int i = 0; i < 8; i++) af[i] = Qs[(ty * 8 + i) * 65 + kk];
#pragma unroll
            for (int j = 0; j < 4; j++) bf[j] = Ks[(tx * 4 + j) * 65 + kk];
#pragma unroll
            for (int i = 0; i < 8; i++)
#pragma unroll
                for (int j = 0; j < 4; j++)
                    sc[i][j] = fmaf(af[i], bf[j], sc[i][j]);
        }

#pragma unroll
        for (int i = 0; i < 8; i++) {
            const float mq = mqs[ty * 8 + i];
            float mx = -INFINITY;
#pragma unroll
            for (int j = 0; j < 4; j++) {
                float m2 = mq * mks[tx * 4 + j];
                float s = sc[i][j] * 0.125f + (1.f - m2) * NEGINF;
                sc[i][j] = s;
                mx = fmaxf(mx, s);
            }
#pragma unroll
            for (int off = 8; off; off >>= 1)
                mx = fmaxf(mx, __shfl_xor_sync(0xffffffffu, mx, off));
            const float mn = fmaxf(m_i[i], mx);
            const float corr = __expf(m_i[i] - mn);
            m_i[i] = mn;
            float rs = 0.f;
#pragma unroll
            for (int j = 0; j < 4; j++) {
                float p = __expf(sc[i][j] - mn);
                Ps[(ty * 8 + i) * 65 + tx * 4 + j] = p;
                rs += p;
            }
#pragma unroll
            for (int off = 8; off; off >>= 1)
                rs += __shfl_xor_sync(0xffffffffu, rs, off);
            l_i[i] = l_i[i] * corr + rs;
#pragma unroll
            for (int j = 0; j < 4; j++) O[i][j] *= corr;
        }
        __syncthreads();

#pragma unroll 4
        for (int kk = 0; kk < 64; kk++) {
            float pf[8];
#pragma unroll
            for (int i = 0; i < 8; i++) pf[i] = Ps[(ty * 8 + i) * 65 + kk];
            float4 v4 = *(const float4*)(Vs + kk * 64 + tx * 4);
            float vf[4] = {v4.x, v4.y, v4.z, v4.w};
#pragma unroll
            for (int i = 0; i < 8; i++)
#pragma unroll
                for (int j = 0; j < 4; j++)
                    O[i][j] = fmaf(pf[i], vf[j], O[i][j]);
        }
    }

#pragma unroll
    for (int i = 0; i < 8; i++) {
        const float inv = 1.f / l_i[i];
        float4 o;
        o.x = O[i][0] * inv;
        o.y = O[i][1] * inv;
        o.z = O[i][2] * inv;
        o.w = O[i][3] * inv;
        *(float4*)(g_ctx +
            ((size_t)((b * S_ + q0 + ty * 8 + i) * H_ + h)) * KD + tx * 4) = o;
    }
}

// ---------------------------------------------------------------------------
extern "C" void kernel_launch(void* const* d_in, const int* in_sizes, int n_in,
                              void* d_out, int out_size)
{
    const float* x  = (const float*)d_in[0];
    const unsigned char* mask = (const unsigned char*)d_in[1];
    const float* Wq = (const float*)d_in[2];
    const float* bq = (const float*)d_in[3];
    const float* Wk = (const float*)d_in[4];
    const float* bk = (const float*)d_in[5];
    const float* Wv = (const float*)d_in[6];
    const float* bv = (const float*)d_in[7];
    const float* Wo = (const float*)d_in[8];
    const float* bo = (const float*)d_in[9];
    float* out = (float*)d_out;

    float *qp, *kp, *vp, *cp;
    cudaGetSymbolAddress((void**)&qp, g_q);
    cudaGetSymbolAddress((void**)&kp, g_k);
    cudaGetSymbolAddress((void**)&vp, g_v);
    cudaGetSymbolAddress((void**)&cp, g_ctx);

    const int smem_bytes =
        (128 * 65 + 64 * 65 + 64 * 64 + 128 * 65 + 128 + 64) * sizeof(float);
    cudaFuncSetAttribute(attn_kernel,
                         cudaFuncAttributeMaxDynamicSharedMemorySize,
                         smem_bytes);

    mask_norm_kernel<<<1, 256>>>(mask);

    dim3 ggrid(8, 64);  // N tiles, M tiles
    gemm_mma_kernel<<<ggrid, 256>>>(x, Wq, bq, qp);
    gemm_mma_kernel<<<ggrid, 256>>>(x, Wk, bk, kp);
    gemm_mma_kernel<<<ggrid, 256>>>(x, Wv, bv, vp);

    attn_kernel<<<dim3(8, 16, 8), 256, smem_bytes>>>();

    gemm_mma_kernel<<<ggrid, 256>>>(cp, Wo, bo, out);
}

// round 14
// speedup vs baseline: 2.0574x; 2.0574x over previous
#include <cuda_runtime.h>
#include <math.h>
#include <stdint.h>

#define B_ 8
#define S_ 1024
#define D_ 1024
#define H_ 16
#define KD 64
#define NEGINF (-1e9f)

// Scratch (allocation-free rule: __device__ globals)
static __device__ float g_q[B_ * S_ * H_ * KD];
static __device__ float g_k[B_ * S_ * H_ * KD];
static __device__ float g_v[B_ * S_ * H_ * KD];
static __device__ float g_ctx[B_ * S_ * H_ * KD];
static __device__ float g_maskf[B_ * S_];

// ---------------------------------------------------------------------------
static __device__ __forceinline__ uint32_t f2tf32(float f) {
    uint32_t u;
    asm("cvt.rna.tf32.f32 %0, %1;" : "=r"(u) : "f"(f));
    return u;
}

static __device__ __forceinline__ void mma_tf32(float* d,
                                                const uint32_t* a,
                                                const uint32_t* b) {
    asm volatile(
        "mma.sync.aligned.m16n8k8.row.col.f32.tf32.tf32.f32 "
        "{%0,%1,%2,%3}, {%4,%5,%6,%7}, {%8,%9}, {%0,%1,%2,%3};"
        : "+f"(d[0]), "+f"(d[1]), "+f"(d[2]), "+f"(d[3])
        : "r"(a[0]), "r"(a[1]), "r"(a[2]), "r"(a[3]),
          "r"(b[0]), "r"(b[1]));
}

// ---------------------------------------------------------------------------
// Mask dtype sniffing + normalization into g_maskf (1.0 / 0.0 per token).
// ---------------------------------------------------------------------------
__global__ void mask_norm_kernel(const unsigned char* __restrict__ m)
{
    __shared__ int mode;  // 1 = 4-byte words, 0 = bytes
    if (threadIdx.x == 0) {
        int any_ge2 = 0, any_off = 0;
        for (int i = 0; i < 512; i++) {
            unsigned char v = m[i];
            if (v >= 2) any_ge2 = 1;
            if ((i & 3) && v) any_off = 1;
        }
        mode = (any_ge2 || !any_off) ? 1 : 0;
    }
    __syncthreads();
    const int n = B_ * S_;
    if (mode) {
        const unsigned int* w = (const unsigned int*)m;
        for (int i = threadIdx.x; i < n; i += blockDim.x)
            g_maskf[i] = w[i] ? 1.f : 0.f;
    } else {
        for (int i = threadIdx.x; i < n; i += blockDim.x)
            g_maskf[i] = m[i] ? 1.f : 0.f;
    }
}

// ---------------------------------------------------------------------------
// tf32 mma.sync GEMM: C[M,N] = A[M,K] @ B[K,N] + bias[N]  (validated R13)
// ---------------------------------------------------------------------------
__global__ __launch_bounds__(256, 2)
void gemm_mma_kernel(const float* __restrict__ A,
                     const float* __restrict__ Bm,
                     const float* __restrict__ bias,
                     float* __restrict__ C)
{
    __shared__ float sA[128][36];
    __shared__ float sB[128][36];

    const int tid = threadIdx.x;
    const int wid = tid >> 5, lane = tid & 31;
    const int bm = blockIdx.y, bn = blockIdx.x;

    const int warp_m = (wid & 1) * 64;
    const int warp_n = (wid >> 1) * 32;
    const int gr = lane >> 2;
    const int tc = lane & 3;

    float acc[4][4][4];
#pragma unroll
    for (int mt = 0; mt < 4; mt++)
#pragma unroll
        for (int nt = 0; nt < 4; nt++)
#pragma unroll
            for (int r = 0; r < 4; r++) acc[mt][nt][r] = 0.f;

    const float* Ap = A + (size_t)(bm * 128) * 1024;
    const float* Bp = Bm + bn * 128;

    const int am = tid >> 3;
    const int ak = (tid & 7) * 4;
    const int nb = tid & 127;
    const int kh = (tid >> 7) * 16;

    for (int k0 = 0; k0 < 1024; k0 += 32) {
#pragma unroll
        for (int p = 0; p < 4; p++) {
            const int m = p * 32 + am;
            float4 v = *(const float4*)(Ap + (size_t)m * 1024 + k0 + ak);
            uint32_t* dst = (uint32_t*)&sA[m][ak];
            dst[0] = f2tf32(v.x);
            dst[1] = f2tf32(v.y);
            dst[2] = f2tf32(v.z);
            dst[3] = f2tf32(v.w);
        }
#pragma unroll
        for (int q = 0; q < 4; q++) {
            const int kk = k0 + kh + q * 4;
            uint32_t* dst = (uint32_t*)&sB[nb][kh + q * 4];
            dst[0] = f2tf32(Bp[(size_t)(kk + 0) * 1024 + nb]);
            dst[1] = f2tf32(Bp[(size_t)(kk + 1) * 1024 + nb]);
            dst[2] = f2tf32(Bp[(size_t)(kk + 2) * 1024 + nb]);
            dst[3] = f2tf32(Bp[(size_t)(kk + 3) * 1024 + nb]);
        }
        __syncthreads();

#pragma unroll
        for (int ks = 0; ks < 4; ks++) {
            const int kq = ks * 8;
            uint32_t af[4][4], bf[4][2];
#pragma unroll
            for (int mt = 0; mt < 4; mt++) {
                const int r = warp_m + mt * 16 + gr;
                af[mt][0] = __float_as_uint(sA[r][kq + tc]);
                af[mt][1] = __float_as_uint(sA[r + 8][kq + tc]);
                af[mt][2] = __float_as_uint(sA[r][kq + tc + 4]);
                af[mt][3] = __float_as_uint(sA[r + 8][kq + tc + 4]);
            }
#pragma unroll
            for (int nt = 0; nt < 4; nt++) {
                const int n = warp_n + nt * 8 + gr;
                bf[nt][0] = __float_as_uint(sB[n][kq + tc]);
                bf[nt][1] = __float_as_uint(sB[n][kq + tc + 4]);
            }
#pragma unroll
            for (int mt = 0; mt < 4; mt++)
#pragma unroll
                for (int nt = 0; nt < 4; nt++)
                    mma_tf32(acc[mt][nt], af[mt], bf[nt]);
        }
        __syncthreads();
    }

#pragma unroll
    for (int mt = 0; mt < 4; mt++) {
        const int row0 = bm * 128 + warp_m + mt * 16 + gr;
#pragma unroll
        for (int nt = 0; nt < 4; nt++) {
            const int col = bn * 128 + warp_n + nt * 8 + 2 * tc;
            const float b0 = bias[col], b1 = bias[col + 1];
            float* c0 = C + (size_t)row0 * 1024 + col;
            float* c1 = C + (size_t)(row0 + 8) * 1024 + col;
            c0[0] = acc[mt][nt][0] + b0;
            c0[1] = acc[mt][nt][1] + b1;
            c1[0] = acc[mt][nt][2] + b0;
            c1[1] = acc[mt][nt][3] + b1;
        }
    }
}

// ---------------------------------------------------------------------------
// tf32 mma.sync flash attention.
// CTA = 256 thr / 8 warps, one (b, h, 128-query tile). Key tiles of 64.
// Each warp owns 16 query rows -> softmax is warp-local (quad shuffles).
// Fragment conventions identical to gemm_mma_kernel (validated).
// SMEM: sQ[128][68] (tf32 bits, pre-scaled 0.125), sK[64][68], sV[64][72].
// ---------------------------------------------------------------------------
__global__ __launch_bounds__(256, 2)
void attn_mma_kernel()
{
    extern __shared__ float sm[];
    float* sQ  = sm;                    // 128*68
    float* sK  = sQ + 128 * 68;         // 64*68
    float* sV  = sK + 64 * 68;          // 64*72
    float* smk = sV + 64 * 72;          // 64

    const int tid = threadIdx.x;
    const int wid = tid >> 5, lane = tid & 31;
    const int g = lane >> 2, tc = lane & 3;
    const int qt = blockIdx.x, h = blockIdx.y, b = blockIdx.z;
    const int q0 = qt * 128;
    const int m0 = wid * 16;

    // Stage Q [128][64], scaled by 0.125 (exact pow2), converted to tf32
#pragma unroll
    for (int p = 0; p < 8; p++) {
        int idx = tid + p * 256;
        int r = idx >> 4, c4 = (idx & 15) << 2;
        float4 v = *(const float4*)(g_q +
            ((size_t)((b * S_ + q0 + r) * H_ + h)) * KD + c4);
        uint32_t* dst = (uint32_t*)(sQ + r * 68 + c4);
        dst[0] = f2tf32(0.125f * v.x);
        dst[1] = f2tf32(0.125f * v.y);
        dst[2] = f2tf32(0.125f * v.z);
        dst[3] = f2tf32(0.125f * v.w);
    }
    const float mq0 = g_maskf[b * S_ + q0 + m0 + g];
    const float mq1 = g_maskf[b * S_ + q0 + m0 + g + 8];
    __syncthreads();

    // Q A-frags resident in registers for all key tiles
    uint32_t Qf[8][4];
    {
        const uint32_t* qb = (const uint32_t*)sQ;
#pragma unroll
        for (int ks = 0; ks < 8; ks++) {
            Qf[ks][0] = qb[(m0 + g) * 68 + ks * 8 + tc];
            Qf[ks][1] = qb[(m0 + g + 8) * 68 + ks * 8 + tc];
            Qf[ks][2] = qb[(m0 + g) * 68 + ks * 8 + tc + 4];
            Qf[ks][3] = qb[(m0 + g + 8) * 68 + ks * 8 + tc + 4];
        }
    }

    float O[8][4];
#pragma unroll
    for (int nt = 0; nt < 8; nt++)
#pragma unroll
        for (int r = 0; r < 4; r++) O[nt][r] = 0.f;
    float m0r = -INFINITY, m1r = -INFINITY, l0 = 0.f, l1 = 0.f;

    const int src0 = (lane & ~3) | (tc >> 1);
    const int src2 = src0 + 2;
    const bool odd = (tc & 1) != 0;

    for (int jt = 0; jt < 16; jt++) {
        const int k0 = jt * 64;
        __syncthreads();  // prior iteration done reading sK/sV
        // Stage K,V tiles [64][64] (tf32 bits)
#pragma unroll
        for (int p = 0; p < 4; p++) {
            int idx = tid + p * 256;
            int r = idx >> 4, c4 = (idx & 15) << 2;
            size_t base = ((size_t)((b * S_ + k0 + r) * H_ + h)) * KD + c4;
            float4 kv = *(const float4*)(g_k + base);
            uint32_t* kd = (uint32_t*)(sK + r * 68 + c4);
            kd[0] = f2tf32(kv.x); kd[1] = f2tf32(kv.y);
            kd[2] = f2tf32(kv.z); kd[3] = f2tf32(kv.w);
            float4 vv = *(const float4*)(g_v + base);
            uint32_t* vd = (uint32_t*)(sV + r * 72 + c4);
            vd[0] = f2tf32(vv.x); vd[1] = f2tf32(vv.y);
            vd[2] = f2tf32(vv.z); vd[3] = f2tf32(vv.w);
        }
        if (tid < 64) smk[tid] = g_maskf[b * S_ + k0 + tid];
        __syncthreads();

        // Scores: S = (0.125*Q) @ K^T  via mma
        float Sf[8][4];
#pragma unroll
        for (int nt = 0; nt < 8; nt++)
#pragma unroll
            for (int r = 0; r < 4; r++) Sf[nt][r] = 0.f;
        const uint32_t* kb = (const uint32_t*)sK;
#pragma unroll
        for (int nt = 0; nt < 8; nt++) {
#pragma unroll
            for (int ks = 0; ks < 8; ks++) {
                uint32_t bfr[2];
                bfr[0] = kb[(nt * 8 + g) * 68 + ks * 8 + tc];
                bfr[1] = kb[(nt * 8 + g) * 68 + ks * 8 + tc + 4];
                mma_tf32(Sf[nt], Qf[ks], bfr);
            }
        }

        // Mask + tile row max (rows g and g+8)
        float tmax0 = -INFINITY, tmax1 = -INFINITY;
#pragma unroll
        for (int nt = 0; nt < 8; nt++) {
            const float mk0 = smk[nt * 8 + 2 * tc];
            const float mk1 = smk[nt * 8 + 2 * tc + 1];
            Sf[nt][0] += (1.f - mq0 * mk0) * NEGINF;
            Sf[nt][1] += (1.f - mq0 * mk1) * NEGINF;
            Sf[nt][2] += (1.f - mq1 * mk0) * NEGINF;
            Sf[nt][3] += (1.f - mq1 * mk1) * NEGINF;
            tmax0 = fmaxf(tmax0, fmaxf(Sf[nt][0], Sf[nt][1]));
            tmax1 = fmaxf(tmax1, fmaxf(Sf[nt][2], Sf[nt][3]));
        }
        tmax0 = fmaxf(tmax0, __shfl_xor_sync(0xffffffffu, tmax0, 1));
        tmax0 = fmaxf(tmax0, __shfl_xor_sync(0xffffffffu, tmax0, 2));
        tmax1 = fmaxf(tmax1, __shfl_xor_sync(0xffffffffu, tmax1, 1));
        tmax1 = fmaxf(tmax1, __shfl_xor_sync(0xffffffffu, tmax1, 2));

        const float nm0 = fmaxf(m0r, tmax0);
        const float nm1 = fmaxf(m1r, tmax1);
        const float corr0 = __expf(m0r - nm0);
        const float corr1 = __expf(m1r - nm1);
        m0r = nm0; m1r = nm1;

        float rs0 = 0.f, rs1 = 0.f;
#pragma unroll
        for (int nt = 0; nt < 8; nt++) {
            Sf[nt][0] = __expf(Sf[nt][0] - nm0); rs0 += Sf[nt][0];
            Sf[nt][1] = __expf(Sf[nt][1] - nm0); rs0 += Sf[nt][1];
            Sf[nt][2] = __expf(Sf[nt][2] - nm1); rs1 += Sf[nt][2];
            Sf[nt][3] = __expf(Sf[nt][3] - nm1); rs1 += Sf[nt][3];
        }
        rs0 += __shfl_xor_sync(0xffffffffu, rs0, 1);
        rs0 += __shfl_xor_sync(0xffffffffu, rs0, 2);
        rs1 += __shfl_xor_sync(0xffffffffu, rs1, 1);
        rs1 += __shfl_xor_sync(0xffffffffu, rs1, 2);
        l0 = l0 * corr0 + rs0;
        l1 = l1 * corr1 + rs1;

#pragma unroll
        for (int nt = 0; nt < 8; nt++) {
            O[nt][0] *= corr0; O[nt][1] *= corr0;
            O[nt][2] *= corr1; O[nt][3] *= corr1;
        }

        // PV: O += P @ V  (P repacked C-frag -> A-frag via quad shuffles)
        const uint32_t* vb = (const uint32_t*)sV;
#pragma unroll
        for (int ks = 0; ks < 8; ks++) {
            float p00 = __shfl_sync(0xffffffffu, Sf[ks][0], src0);
            float p01 = __shfl_sync(0xffffffffu, Sf[ks][1], src0);
            float p10 = __shfl_sync(0xffffffffu, Sf[ks][2], src0);
            float p11 = __shfl_sync(0xffffffffu, Sf[ks][3], src0);
            float p20 = __shfl_sync(0xffffffffu, Sf[ks][0], src2);
            float p21 = __shfl_sync(0xffffffffu, Sf[ks][1], src2);
            float p30 = __shfl_sync(0xffffffffu, Sf[ks][2], src2);
            float p31 = __shfl_sync(0xffffffffu, Sf[ks][3], src2);
            uint32_t Af[4];
            Af[0] = f2tf32(odd ? p01 : p00);
            Af[1] = f2tf32(odd ? p11 : p10);
            Af[2] = f2tf32(odd ? p21 : p20);
            Af[3] = f2tf32(odd ? p31 : p30);
#pragma unroll
            for (int nt = 0; nt < 8; nt++) {
                uint32_t bfr[2];
                bfr[0] = vb[(ks * 8 + tc) * 72 + nt * 8 + g];
                bfr[1] = vb[(ks * 8 + tc + 4) * 72 + nt * 8 + g];
                mma_tf32(O[nt], Af, bfr);
            }
        }
    }

    // Normalize and write ctx [B,S,H,KD]
    const float inv0 = 1.f / l0, inv1 = 1.f / l1;
    const size_t row0 = (size_t)(b * S_ + q0 + m0 + g);
#pragma unroll
    for (int nt = 0; nt < 8; nt++) {
        const int col = nt * 8 + 2 * tc;
        float2 o0 = make_float2(O[nt][0] * inv0, O[nt][1] * inv0);
        float2 o1 = make_float2(O[nt][2] * inv1, O[nt][3] * inv1);
        *(float2*)(g_ctx + (row0 * H_ + h) * KD + col) = o0;
        *(float2*)(g_ctx + ((row0 + 8) * H_ + h) * KD + col) = o1;
    }
}

// ---------------------------------------------------------------------------
extern "C" void kernel_launch(void* const* d_in, const int* in_sizes, int n_in,
                              void* d_out, int out_size)
{
    const float* x  = (const float*)d_in[0];
    const unsigned char* mask = (const unsigned char*)d_in[1];
    const float* Wq = (const float*)d_in[2];
    const float* bq = (const float*)d_in[3];
    const float* Wk = (const float*)d_in[4];
    const float* bk = (const float*)d_in[5];
    const float* Wv = (const float*)d_in[6];
    const float* bv = (const float*)d_in[7];
    const float* Wo = (const float*)d_in[8];
    const float* bo = (const float*)d_in[9];
    float* out = (float*)d_out;

    float *qp, *kp, *vp, *cp;
    cudaGetSymbolAddress((void**)&qp, g_q);
    cudaGetSymbolAddress((void**)&kp, g_k);
    cudaGetSymbolAddress((void**)&vp, g_v);
    cudaGetSymbolAddress((void**)&cp, g_ctx);

    const int attn_smem =
        (128 * 68 + 64 * 68 + 64 * 72 + 64) * sizeof(float);
    cudaFuncSetAttribute(attn_mma_kernel,
                         cudaFuncAttributeMaxDynamicSharedMemorySize,
                         attn_smem);

    mask_norm_kernel<<<1, 256>>>(mask);

    dim3 ggrid(8, 64);  // N tiles, M tiles
    gemm_mma_kernel<<<ggrid, 256>>>(x, Wq, bq, qp);
    gemm_mma_kernel<<<ggrid, 256>>>(x, Wk, bk, kp);
    gemm_mma_kernel<<<ggrid, 256>>>(x, Wv, bv, vp);

    attn_mma_kernel<<<dim3(8, H_, B_), 256, attn_smem>>>();

    gemm_mma_kernel<<<ggrid, 256>>>(cp, Wo, bo, out);
}

// round 15
// speedup vs baseline: 2.1872x; 1.0631x over previous
#include <cuda_runtime.h>
#include <math.h>
#include <stdint.h>

#define B_ 8
#define S_ 1024
#define D_ 1024
#define H_ 16
#define KD 64
#define NEGINF (-1e9f)

// Scratch (allocation-free rule: __device__ globals)
static __device__ float g_q[B_ * S_ * H_ * KD];
static __device__ float g_k[B_ * S_ * H_ * KD];
static __device__ float g_v[B_ * S_ * H_ * KD];
static __device__ float g_ctx[B_ * S_ * H_ * KD];
static __device__ float g_maskf[B_ * S_];

// ---------------------------------------------------------------------------
static __device__ __forceinline__ uint32_t f2tf32(float f) {
    uint32_t u;
    asm("cvt.rna.tf32.f32 %0, %1;" : "=r"(u) : "f"(f));
    return u;
}

static __device__ __forceinline__ void mma_tf32(float* d,
                                                const uint32_t* a,
                                                const uint32_t* b) {
    asm volatile(
        "mma.sync.aligned.m16n8k8.row.col.f32.tf32.tf32.f32 "
        "{%0,%1,%2,%3}, {%4,%5,%6,%7}, {%8,%9}, {%0,%1,%2,%3};"
        : "+f"(d[0]), "+f"(d[1]), "+f"(d[2]), "+f"(d[3])
        : "r"(a[0]), "r"(a[1]), "r"(a[2]), "r"(a[3]),
          "r"(b[0]), "r"(b[1]));
}

static __device__ __forceinline__ uint32_t smem_u32(const void* p) {
    uint32_t a;
    asm("{ .reg .u64 t; cvta.to.shared.u64 t, %1; cvt.u32.u64 %0, t; }"
        : "=r"(a) : "l"(p));
    return a;
}

static __device__ __forceinline__ void cp_async16(uint32_t dst,
                                                  const void* src) {
    asm volatile("cp.async.cg.shared.global [%0], [%1], 16;"
                 :: "r"(dst), "l"(src));
}
#define CP_COMMIT() asm volatile("cp.async.commit_group;" ::: "memory")
#define CP_WAIT0()  asm volatile("cp.async.wait_group 0;" ::: "memory")

// ---------------------------------------------------------------------------
// Mask dtype sniffing + normalization into g_maskf (1.0 / 0.0 per token).
// ---------------------------------------------------------------------------
__global__ void mask_norm_kernel(const unsigned char* __restrict__ m)
{
    __shared__ int mode;  // 1 = 4-byte words, 0 = bytes
    if (threadIdx.x == 0) {
        int any_ge2 = 0, any_off = 0;
        for (int i = 0; i < 512; i++) {
            unsigned char v = m[i];
            if (v >= 2) any_ge2 = 1;
            if ((i & 3) && v) any_off = 1;
        }
        mode = (any_ge2 || !any_off) ? 1 : 0;
    }
    __syncthreads();
    const int n = B_ * S_;
    if (mode) {
        const unsigned int* w = (const unsigned int*)m;
        for (int i = threadIdx.x; i < n; i += blockDim.x)
            g_maskf[i] = w[i] ? 1.f : 0.f;
    } else {
        for (int i = threadIdx.x; i < n; i += blockDim.x)
            g_maskf[i] = m[i] ? 1.f : 0.f;
    }
}

// ---------------------------------------------------------------------------
// tf32 mma.sync GEMM, cp.async double-buffered, QKV-fused (blockIdx.z picks
// W/bias/C). C[M,N] = A[M,K] @ W[K,N] + bias[N]; M=8192, N=K=1024.
// CTA 128x128, BK=32, 8 warps x (64x32) warp tiles.
// SMEM: sA[2][128][36] raw fp32, sB[2][32][136] raw fp32 (natural [k][n]).
// cvt.rna.tf32 applied at fragment load (numerics identical to R13/14).
// ---------------------------------------------------------------------------
#define SA_OFF(buf) ((buf) * 128 * 36)
#define SB_OFF(buf) ((buf) * 32 * 136)

__global__ __launch_bounds__(256, 2)
void gemm_mma_kernel(const float* __restrict__ A,
                     const float* __restrict__ W0,
                     const float* __restrict__ W1,
                     const float* __restrict__ W2,
                     const float* __restrict__ b0p,
                     const float* __restrict__ b1p,
                     const float* __restrict__ b2p,
                     float* __restrict__ C0,
                     float* __restrict__ C1,
                     float* __restrict__ C2)
{
    extern __shared__ float smem[];
    float* sA = smem;                  // 2*128*36 floats
    float* sB = smem + 2 * 128 * 36;   // 2*32*136 floats

    const int z = blockIdx.z;
    const float* Bm   = (z == 0) ? W0 : (z == 1) ? W1 : W2;
    const float* bias = (z == 0) ? b0p : (z == 1) ? b1p : b2p;
    float* C          = (z == 0) ? C0 : (z == 1) ? C1 : C2;

    const int tid = threadIdx.x;
    const int wid = tid >> 5, lane = tid & 31;
    const int bm = blockIdx.y, bn = blockIdx.x;

    const int warp_m = (wid & 1) * 64;
    const int warp_n = (wid >> 1) * 32;
    const int gr = lane >> 2;
    const int tc = lane & 3;

    float acc[4][4][4];
#pragma unroll
    for (int mt = 0; mt < 4; mt++)
#pragma unroll
        for (int nt = 0; nt < 4; nt++)
#pragma unroll
            for (int r = 0; r < 4; r++) acc[mt][nt][r] = 0.f;

    const float* Ap = A + (size_t)(bm * 128) * 1024;
    const float* Bp = Bm + bn * 128;

    const uint32_t sA_u = smem_u32(sA);
    const uint32_t sB_u = smem_u32(sB);

    // per-thread copy coordinates (4 x 16B for A, 4 x 16B for B)
    int ar[4], ac[4], br[4], bc[4];
#pragma unroll
    for (int p = 0; p < 4; p++) {
        int idx = tid + p * 256;
        ar[p] = idx >> 3;            // 0..127
        ac[p] = (idx & 7) << 2;      // 0..28
        br[p] = idx >> 5;            // 0..31
        bc[p] = (idx & 31) << 2;     // 0..124
    }

    // prologue: stage chunk 0 into buffer 0
#pragma unroll
    for (int p = 0; p < 4; p++) {
        cp_async16(sA_u + (SA_OFF(0) + ar[p] * 36 + ac[p]) * 4,
                   Ap + (size_t)ar[p] * 1024 + ac[p]);
        cp_async16(sB_u + (SB_OFF(0) + br[p] * 136 + bc[p]) * 4,
                   Bp + (size_t)br[p] * 1024 + bc[p]);
    }
    CP_COMMIT();

    for (int ic = 0; ic < 32; ic++) {
        const int buf = ic & 1;
        CP_WAIT0();
        __syncthreads();  // chunk ic landed everywhere; prior compute done

        if (ic < 31) {
            const int k0n = (ic + 1) * 32;
            const int nb = buf ^ 1;
#pragma unroll
            for (int p = 0; p < 4; p++) {
                cp_async16(sA_u + (SA_OFF(nb) + ar[p] * 36 + ac[p]) * 4,
                           Ap + (size_t)ar[p] * 1024 + k0n + ac[p]);
                cp_async16(sB_u + (SB_OFF(nb) + br[p] * 136 + bc[p]) * 4,
                           Bp + (size_t)(k0n + br[p]) * 1024 + bc[p]);
            }
            CP_COMMIT();
        }

        const float* sAb = sA + SA_OFF(buf);
        const float* sBb = sB + SB_OFF(buf);
#pragma unroll
        for (int ks = 0; ks < 4; ks++) {
            const int kq = ks * 8;
            uint32_t af[4][4], bf[4][2];
#pragma unroll
            for (int mt = 0; mt < 4; mt++) {
                const int r = warp_m + mt * 16 + gr;
                af[mt][0] = f2tf32(sAb[r * 36 + kq + tc]);
                af[mt][1] = f2tf32(sAb[(r + 8) * 36 + kq + tc]);
                af[mt][2] = f2tf32(sAb[r * 36 + kq + tc + 4]);
                af[mt][3] = f2tf32(sAb[(r + 8) * 36 + kq + tc + 4]);
            }
#pragma unroll
            for (int nt = 0; nt < 4; nt++) {
                const int n = warp_n + nt * 8 + gr;
                bf[nt][0] = f2tf32(sBb[(kq + tc) * 136 + n]);
                bf[nt][1] = f2tf32(sBb[(kq + tc + 4) * 136 + n]);
            }
#pragma unroll
            for (int mt = 0; mt < 4; mt++)
#pragma unroll
                for (int nt = 0; nt < 4; nt++)
                    mma_tf32(acc[mt][nt], af[mt], bf[nt]);
        }
    }

#pragma unroll
    for (int mt = 0; mt < 4; mt++) {
        const int row0 = bm * 128 + warp_m + mt * 16 + gr;
#pragma unroll
        for (int nt = 0; nt < 4; nt++) {
            const int col = bn * 128 + warp_n + nt * 8 + 2 * tc;
            const float bb0 = bias[col], bb1 = bias[col + 1];
            float* c0 = C + (size_t)row0 * 1024 + col;
            float* c1 = C + (size_t)(row0 + 8) * 1024 + col;
            c0[0] = acc[mt][nt][0] + bb0;
            c0[1] = acc[mt][nt][1] + bb1;
            c1[0] = acc[mt][nt][2] + bb0;
            c1[1] = acc[mt][nt][3] + bb1;
        }
    }
}

// ---------------------------------------------------------------------------
// tf32 mma.sync flash attention (validated R14).
// ---------------------------------------------------------------------------
__global__ __launch_bounds__(256, 2)
void attn_mma_kernel()
{
    extern __shared__ float sm[];
    float* sQ  = sm;                    // 128*68
    float* sK  = sQ + 128 * 68;         // 64*68
    float* sV  = sK + 64 * 68;          // 64*72
    float* smk = sV + 64 * 72;          // 64

    const int tid = threadIdx.x;
    const int wid = tid >> 5, lane = tid & 31;
    const int g = lane >> 2, tc = lane & 3;
    const int qt = blockIdx.x, h = blockIdx.y, b = blockIdx.z;
    const int q0 = qt * 128;
    const int m0 = wid * 16;

#pragma unroll
    for (int p = 0; p < 8; p++) {
        int idx = tid + p * 256;
        int r = idx >> 4, c4 = (idx & 15) << 2;
        float4 v = *(const float4*)(g_q +
            ((size_t)((b * S_ + q0 + r) * H_ + h)) * KD + c4);
        uint32_t* dst = (uint32_t*)(sQ + r * 68 + c4);
        dst[0] = f2tf32(0.125f * v.x);
        dst[1] = f2tf32(0.125f * v.y);
        dst[2] = f2tf32(0.125f * v.z);
        dst[3] = f2tf32(0.125f * v.w);
    }
    const float mq0 = g_maskf[b * S_ + q0 + m0 + g];
    const float mq1 = g_maskf[b * S_ + q0 + m0 + g + 8];
    __syncthreads();

    uint32_t Qf[8][4];
    {
        const uint32_t* qb = (const uint32_t*)sQ;
#pragma unroll
        for (int ks = 0; ks < 8; ks++) {
            Qf[ks][0] = qb[(m0 + g) * 68 + ks * 8 + tc];
            Qf[ks][1] = qb[(m0 + g + 8) * 68 + ks * 8 + tc];
            Qf[ks][2] = qb[(m0 + g) * 68 + ks * 8 + tc + 4];
            Qf[ks][3] = qb[(m0 + g + 8) * 68 + ks * 8 + tc + 4];
        }
    }

    float O[8][4];
#pragma unroll
    for (int nt = 0; nt < 8; nt++)
#pragma unroll
        for (int r = 0; r < 4; r++) O[nt][r] = 0.f;
    float m0r = -INFINITY, m1r = -INFINITY, l0 = 0.f, l1 = 0.f;

    const int src0 = (lane & ~3) | (tc >> 1);
    const int src2 = src0 + 2;
    const bool odd = (tc & 1) != 0;

    for (int jt = 0; jt < 16; jt++) {
        const int k0 = jt * 64;
        __syncthreads();
#pragma unroll
        for (int p = 0; p < 4; p++) {
            int idx = tid + p * 256;
            int r = idx >> 4, c4 = (idx & 15) << 2;
            size_t base = ((size_t)((b * S_ + k0 + r) * H_ + h)) * KD + c4;
            float4 kv = *(const float4*)(g_k + base);
            uint32_t* kd = (uint32_t*)(sK + r * 68 + c4);
            kd[0] = f2tf32(kv.x); kd[1] = f2tf32(kv.y);
            kd[2] = f2tf32(kv.z); kd[3] = f2tf32(kv.w);
            float4 vv = *(const float4*)(g_v + base);
            uint32_t* vd = (uint32_t*)(sV + r * 72 + c4);
            vd[0] = f2tf32(vv.x); vd[1] = f2tf32(vv.y);
            vd[2] = f2tf32(vv.z); vd[3] = f2tf32(vv.w);
        }
        if (tid < 64) smk[tid] = g_maskf[b * S_ + k0 + tid];
        __syncthreads();

        float Sf[8][4];
#pragma unroll
        for (int nt = 0; nt < 8; nt++)
#pragma unroll
            for (int r = 0; r < 4; r++) Sf[nt][r] = 0.f;
        const uint32_t* kb = (const uint32_t*)sK;
#pragma unroll
        for (int nt = 0; nt < 8; nt++) {
#pragma unroll
            for (int ks = 0; ks < 8; ks++) {
                uint32_t bfr[2];
                bfr[0] = kb[(nt * 8 + g) * 68 + ks * 8 + tc];
                bfr[1] = kb[(nt * 8 + g) * 68 + ks * 8 + tc + 4];
                mma_tf32(Sf[nt], Qf[ks], bfr);
            }
        }

        float tmax0 = -INFINITY, tmax1 = -INFINITY;
#pragma unroll
        for (int nt = 0; nt < 8; nt++) {
            const float mk0 = smk[nt * 8 + 2 * tc];
            const float mk1 = smk[nt * 8 + 2 * tc + 1];
            Sf[nt][0] += (1.f - mq0 * mk0) * NEGINF;
            Sf[nt][1] += (1.f - mq0 * mk1) * NEGINF;
            Sf[nt][2] += (1.f - mq1 * mk0) * NEGINF;
            Sf[nt][3] += (1.f - mq1 * mk1) * NEGINF;
            tmax0 = fmaxf(tmax0, fmaxf(Sf[nt][0], Sf[nt][1]));
            tmax1 = fmaxf(tmax1, fmaxf(Sf[nt][2], Sf[nt][3]));
        }
        tmax0 = fmaxf(tmax0, __shfl_xor_sync(0xffffffffu, tmax0, 1));
        tmax0 = fmaxf(tmax0, __shfl_xor_sync(0xffffffffu, tmax0, 2));
        tmax1 = fmaxf(tmax1, __shfl_xor_sync(0xffffffffu, tmax1, 1));
        tmax1 = fmaxf(tmax1, __shfl_xor_sync(0xffffffffu, tmax1, 2));

        const float nm0 = fmaxf(m0r, tmax0);
        const float nm1 = fmaxf(m1r, tmax1);
        const float corr0 = __expf(m0r - nm0);
        const float corr1 = __expf(m1r - nm1);
        m0r = nm0; m1r = nm1;

        float rs0 = 0.f, rs1 = 0.f;
#pragma unroll
        for (int nt = 0; nt < 8; nt++) {
            Sf[nt][0] = __expf(Sf[nt][0] - nm0); rs0 += Sf[nt][0];
            Sf[nt][1] = __expf(Sf[nt][1] - nm0); rs0 += Sf[nt][1];
            Sf[nt][2] = __expf(Sf[nt][2] - nm1); rs1 += Sf[nt][2];
            Sf[nt][3] = __expf(Sf[nt][3] - nm1); rs1 += Sf[nt][3];
        }
        rs0 += __shfl_xor_sync(0xffffffffu, rs0, 1);
        rs0 += __shfl_xor_sync(0xffffffffu, rs0, 2);
        rs1 += __shfl_xor_sync(0xffffffffu, rs1, 1);
        rs1 += __shfl_xor_sync(0xffffffffu, rs1, 2);
        l0 = l0 * corr0 + rs0;
        l1 = l1 * corr1 + rs1;

#pragma unroll
        for (int nt = 0; nt < 8; nt++) {
            O[nt][0] *= corr0; O[nt][1] *= corr0;
            O[nt][2] *= corr1; O[nt][3] *= corr1;
        }

        const uint32_t* vb = (const uint32_t*)sV;
#pragma unroll
        for (int ks = 0; ks < 8; ks++) {
            float p00 = __shfl_sync(0xffffffffu, Sf[ks][0], src0);
            float p01 = __shfl_sync(0xffffffffu, Sf[ks][1], src0);
            float p10 = __shfl_sync(0xffffffffu, Sf[ks][2], src0);
            float p11 = __shfl_sync(0xffffffffu, Sf[ks][3], src0);
            float p20 = __shfl_sync(0xffffffffu, Sf[ks][0], src2);
            float p21 = __shfl_sync(0xffffffffu, Sf[ks][1], src2);
            float p30 = __shfl_sync(0xffffffffu, Sf[ks][2], src2);
            float p31 = __shfl_sync(0xffffffffu, Sf[ks][3], src2);
            uint32_t Af[4];
            Af[0] = f2tf32(odd ? p01 : p00);
            Af[1] = f2tf32(odd ? p11 : p10);
            Af[2] = f2tf32(odd ? p21 : p20);
            Af[3] = f2tf32(odd ? p31 : p30);
#pragma unroll
            for (int nt = 0; nt < 8; nt++) {
                uint32_t bfr[2];
                bfr[0] = vb[(ks * 8 + tc) * 72 + nt * 8 + g];
                bfr[1] = vb[(ks * 8 + tc + 4) * 72 + nt * 8 + g];
                mma_tf32(O[nt], Af, bfr);
            }
        }
    }

    const float inv0 = 1.f / l0, inv1 = 1.f / l1;
    const size_t row0 = (size_t)(b * S_ + q0 + m0 + g);
#pragma unroll
    for (int nt = 0; nt < 8; nt++) {
        const int col = nt * 8 + 2 * tc;
        float2 o0 = make_float2(O[nt][0] * inv0, O[nt][1] * inv0);
        float2 o1 = make_float2(O[nt][2] * inv1, O[nt][3] * inv1);
        *(float2*)(g_ctx + (row0 * H_ + h) * KD + col) = o0;
        *(float2*)(g_ctx + ((row0 + 8) * H_ + h) * KD + col) = o1;
    }
}

// ---------------------------------------------------------------------------
extern "C" void kernel_launch(void* const* d_in, const int* in_sizes, int n_in,
                              void* d_out, int out_size)
{
    const float* x  = (const float*)d_in[0];
    const unsigned char* mask = (const unsigned char*)d_in[1];
    const float* Wq = (const float*)d_in[2];
    const float* bq = (const float*)d_in[3];
    const float* Wk = (const float*)d_in[4];
    const float* bk = (const float*)d_in[5];
    const float* Wv = (const float*)d_in[6];
    const float* bv = (const float*)d_in[7];
    const float* Wo = (const float*)d_in[8];
    const float* bo = (const float*)d_in[9];
    float* out = (float*)d_out;

    float *qp, *kp, *vp, *cp;
    cudaGetSymbolAddress((void**)&qp, g_q);
    cudaGetSymbolAddress((void**)&kp, g_k);
    cudaGetSymbolAddress((void**)&vp, g_v);
    cudaGetSymbolAddress((void**)&cp, g_ctx);

    const int gemm_smem = (2 * 128 * 36 + 2 * 32 * 136) * sizeof(float);
    cudaFuncSetAttribute(gemm_mma_kernel,
                         cudaFuncAttributeMaxDynamicSharedMemorySize,
                         gemm_smem);
    const int attn_smem =
        (128 * 68 + 64 * 68 + 64 * 72 + 64) * sizeof(float);
    cudaFuncSetAttribute(attn_mma_kernel,
                         cudaFuncAttributeMaxDynamicSharedMemorySize,
                         attn_smem);

    mask_norm_kernel<<<1, 256>>>(mask);

    // Fused QKV: z selects (Wq,bq,q) / (Wk,bk,k) / (Wv,bv,v)
    gemm_mma_kernel<<<dim3(8, 64, 3), 256, gemm_smem>>>(
        x, Wq, Wk, Wv, bq, bk, bv, qp, kp, vp);

    attn_mma_kernel<<<dim3(8, H_, B_), 256, attn_smem>>>();

    gemm_mma_kernel<<<dim3(8, 64, 1), 256, gemm_smem>>>(
        cp, Wo, Wo, Wo, bo, bo, bo, out, out, out);
}

// round 16
// speedup vs baseline: 2.6569x; 1.2147x over previous
#include <cuda_runtime.h>
#include <math.h>
#include <stdint.h>

#define B_ 8
#define S_ 1024
#define D_ 1024
#define H_ 16
#define KD 64
#define NEGINF (-1e9f)

// Scratch (allocation-free rule: __device__ globals)
static __device__ float g_q[B_ * S_ * H_ * KD];
static __device__ float g_k[B_ * S_ * H_ * KD];
static __device__ float g_v[B_ * S_ * H_ * KD];
static __device__ float g_maskf[B_ * S_];
// Fragment-layout tf32 buffers
static __device__ uint32_t g_xf[B_ * S_ * D_];        // x,  AF layout
static __device__ uint32_t g_cxf[B_ * S_ * H_ * KD];  // ctx, AF layout
static __device__ uint32_t g_wf[4 * D_ * H_ * KD];    // Wq,Wk,Wv,Wo WF layout

// AF layout: [m16 (M/16)][ks (K/8)][lane 32][r 4]
//   lane = (m&7)*4 + (k&3);  r = ((k&4)>>1) | ((m&8)>>3)
// WF layout: [n8 (N/8)][ks (K/8)][lane 32][q 2]
//   lane = (n&7)*4 + (k&3);  q = (k&4)>>2

// ---------------------------------------------------------------------------
static __device__ __forceinline__ uint32_t f2tf32(float f) {
    uint32_t u;
    asm("cvt.rna.tf32.f32 %0, %1;" : "=r"(u) : "f"(f));
    return u;
}

static __device__ __forceinline__ void mma_tf32(float* d,
                                                const uint32_t* a,
                                                const uint32_t* b) {
    asm volatile(
        "mma.sync.aligned.m16n8k8.row.col.f32.tf32.tf32.f32 "
        "{%0,%1,%2,%3}, {%4,%5,%6,%7}, {%8,%9}, {%0,%1,%2,%3};"
        : "+f"(d[0]), "+f"(d[1]), "+f"(d[2]), "+f"(d[3])
        : "r"(a[0]), "r"(a[1]), "r"(a[2]), "r"(a[3]),
          "r"(b[0]), "r"(b[1]));
}

static __device__ __forceinline__ uint32_t smem_u32(const void* p) {
    uint32_t a;
    asm("{ .reg .u64 t; cvta.to.shared.u64 t, %1; cvt.u32.u64 %0, t; }"
        : "=r"(a) : "l"(p));
    return a;
}

static __device__ __forceinline__ void cp_async16(uint32_t dst,
                                                  const void* src) {
    asm volatile("cp.async.cg.shared.global [%0], [%1], 16;"
                 :: "r"(dst), "l"(src));
}
#define CP_COMMIT() asm volatile("cp.async.commit_group;" ::: "memory")
#define CP_WAIT0()  asm volatile("cp.async.wait_group 0;" ::: "memory")

// ---------------------------------------------------------------------------
// Mask dtype sniffing + normalization into g_maskf.
// ---------------------------------------------------------------------------
__global__ void mask_norm_kernel(const unsigned char* __restrict__ m)
{
    __shared__ int mode;
    if (threadIdx.x == 0) {
        int any_ge2 = 0, any_off = 0;
        for (int i = 0; i < 512; i++) {
            unsigned char v = m[i];
            if (v >= 2) any_ge2 = 1;
            if ((i & 3) && v) any_off = 1;
        }
        mode = (any_ge2 || !any_off) ? 1 : 0;
    }
    __syncthreads();
    const int n = B_ * S_;
    if (mode) {
        const unsigned int* w = (const unsigned int*)m;
        for (int i = threadIdx.x; i < n; i += blockDim.x)
            g_maskf[i] = w[i] ? 1.f : 0.f;
    } else {
        for (int i = threadIdx.x; i < n; i += blockDim.x)
            g_maskf[i] = m[i] ? 1.f : 0.f;
    }
}

// ---------------------------------------------------------------------------
// x [8192][1024] fp32 -> g_xf AF layout (tf32). One uint4 per thread.
// ---------------------------------------------------------------------------
__global__ __launch_bounds__(256)
void xconv_kernel(const float* __restrict__ x)
{
    const int idx = blockIdx.x * 256 + threadIdx.x;  // 0..2M-1
    const int lane = idx & 31;
    const int ks = (idx >> 5) & 127;
    const int m16 = idx >> 12;
    const int m = m16 * 16 + (lane >> 2);
    const int k = ks * 8 + (lane & 3);
    const float* p0 = x + (size_t)m * 1024 + k;
    uint4 o;
    o.x = f2tf32(p0[0]);
    o.y = f2tf32(p0[8 * 1024]);
    o.z = f2tf32(p0[4]);
    o.w = f2tf32(p0[8 * 1024 + 4]);
    ((uint4*)g_xf)[idx] = o;
}

// ---------------------------------------------------------------------------
// W [1024][1024] fp32 (4 of them) -> g_wf WF layout (tf32). uint2 per thread.
// ---------------------------------------------------------------------------
__global__ __launch_bounds__(256)
void wconv_kernel(const float* __restrict__ W0,
                  const float* __restrict__ W1,
                  const float* __restrict__ W2,
                  const float* __restrict__ W3)
{
    const int w = blockIdx.y;
    const float* W = (w == 0) ? W0 : (w == 1) ? W1 : (w == 2) ? W2 : W3;
    const int idx = blockIdx.x * 256 + threadIdx.x;  // 0..512K-1
    const int lane = idx & 31;
    const int ks = (idx >> 5) & 127;
    const int n8 = idx >> 12;
    const int k = ks * 8 + (lane & 3);
    const int n = n8 * 8 + (lane >> 2);
    uint2 o;
    o.x = f2tf32(W[(size_t)k * 1024 + n]);
    o.y = f2tf32(W[(size_t)(k + 4) * 1024 + n]);
    ((uint2*)(g_wf + (size_t)w * 1024 * 1024))[idx] = o;
}

// ---------------------------------------------------------------------------
// tf32 mma.sync GEMM, frag-ready operands, cp.async double-buffered.
// C[M,N] = A @ W + bias; M=8192, N=K=1024. CTA 128x128, BK=32.
// SMEM chunk: sA [m16l 8][ks 4][lane 32][r 4] u32 (16KB),
//             sB [n8l 16][ks 4][lane 32][q 2] u32 (16KB), x2 buffers.
// Zero cvt, zero scalar LDS in main loop.
// ---------------------------------------------------------------------------
__global__ __launch_bounds__(256, 2)
void gemm_frag_kernel(const uint32_t* __restrict__ AF,
                      const uint32_t* __restrict__ WFbase, int wsel,
                      const float* __restrict__ b0p,
                      const float* __restrict__ b1p,
                      const float* __restrict__ b2p,
                      float* __restrict__ C0,
                      float* __restrict__ C1,
                      float* __restrict__ C2)
{
    extern __shared__ uint32_t smem[];
    // sA: smem[0 .. 2*4096), sB: smem[8192 .. 8192+2*4096)

    const int z = blockIdx.z;
    const uint32_t* WF = WFbase + (size_t)(wsel + z) * 1024 * 1024;
    const float* bias = (z == 0) ? b0p : (z == 1) ? b1p : b2p;
    float* C          = (z == 0) ? C0 : (z == 1) ? C1 : C2;

    const int tid = threadIdx.x;
    const int wid = tid >> 5, lane = tid & 31;
    const int bm = blockIdx.y, bn = blockIdx.x;

    const int gr = lane >> 2;
    const int tc = lane & 3;

    float acc[4][4][4];
#pragma unroll
    for (int mt = 0; mt < 4; mt++)
#pragma unroll
        for (int nt = 0; nt < 4; nt++)
#pragma unroll
            for (int r = 0; r < 4; r++) acc[mt][nt][r] = 0.f;

    const uint32_t sA_u = smem_u32(smem);
    const uint32_t sB_u = sA_u + 32768;

    const char* AFb = (const char*)AF;
    const char* WFb = (const char*)WF;

    // prologue: chunk 0 -> buffer 0
#pragma unroll
    for (int p = 0; p < 4; p++) {
        const int off = tid * 16 + p * 4096;
        const int m16l = off >> 11, ainner = off & 2047;
        cp_async16(sA_u + off,
                   AFb + ((size_t)(bm * 8 + m16l) * 128 + 0) * 512 + ainner);
        const int n8l = off >> 10, binner = off & 1023;
        cp_async16(sB_u + off,
                   WFb + ((size_t)(bn * 16 + n8l) * 128 + 0) * 256 + binner);
    }
    CP_COMMIT();

    for (int ic = 0; ic < 32; ic++) {
        const int buf = ic & 1;
        CP_WAIT0();
        __syncthreads();

        if (ic < 31) {
            const int ks0 = (ic + 1) * 4;
            const int nbuf = (buf ^ 1) * 16384;
#pragma unroll
            for (int p = 0; p < 4; p++) {
                const int off = tid * 16 + p * 4096;
                const int m16l = off >> 11, ainner = off & 2047;
                cp_async16(sA_u + nbuf + off,
                           AFb + ((size_t)(bm * 8 + m16l) * 128 + ks0) * 512 +
                               ainner);
                const int n8l = off >> 10, binner = off & 1023;
                cp_async16(sB_u + nbuf + off,
                           WFb + ((size_t)(bn * 16 + n8l) * 128 + ks0) * 256 +
                               binner);
            }
            CP_COMMIT();
        }

        const uint32_t* sAb = smem + buf * 4096;
        const uint32_t* sBb = smem + 8192 + buf * 4096;
        const int am = (wid & 1) * 4;   // m16l base
        const int bn8 = (wid >> 1) * 4; // n8l base
#pragma unroll
        for (int ks = 0; ks < 4; ks++) {
            uint4 af[4];
            uint2 bf[4];
#pragma unroll
            for (int mt = 0; mt < 4; mt++)
                af[mt] = *(const uint4*)(sAb +
                    (((am + mt) * 4 + ks) * 32 + lane) * 4);
#pragma unroll
            for (int nt = 0; nt < 4; nt++)
                bf[nt] = *(const uint2*)(sBb +
                    (((bn8 + nt) * 4 + ks) * 32 + lane) * 2);
#pragma unroll
            for (int mt = 0; mt < 4; mt++)
#pragma unroll
                for (int nt = 0; nt < 4; nt++)
                    mma_tf32(acc[mt][nt], (const uint32_t*)&af[mt],
                             (const uint32_t*)&bf[nt]);
        }
    }

    const int warp_m = (wid & 1) * 64;
    const int warp_n = (wid >> 1) * 32;
#pragma unroll
    for (int mt = 0; mt < 4; mt++) {
        const int row0 = bm * 128 + warp_m + mt * 16 + gr;
#pragma unroll
        for (int nt = 0; nt < 4; nt++) {
            const int col = bn * 128 + warp_n + nt * 8 + 2 * tc;
            const float bb0 = bias[col], bb1 = bias[col + 1];
            float* c0 = C + (size_t)row0 * 1024 + col;
            float* c1 = C + (size_t)(row0 + 8) * 1024 + col;
            c0[0] = acc[mt][nt][0] + bb0;
            c0[1] = acc[mt][nt][1] + bb1;
            c1[0] = acc[mt][nt][2] + bb0;
            c1[1] = acc[mt][nt][3] + bb1;
        }
    }
}

// ---------------------------------------------------------------------------
// tf32 mma.sync flash attention (validated R14/15). Output -> g_cxf (AF).
// ---------------------------------------------------------------------------
__global__ __launch_bounds__(256, 2)
void attn_mma_kernel()
{
    extern __shared__ float sm[];
    float* sQ  = sm;                    // 128*68
    float* sK  = sQ + 128 * 68;         // 64*68
    float* sV  = sK + 64 * 68;          // 64*72
    float* smk = sV + 64 * 72;          // 64

    const int tid = threadIdx.x;
    const int wid = tid >> 5, lane = tid & 31;
    const int g = lane >> 2, tc = lane & 3;
    const int qt = blockIdx.x, h = blockIdx.y, b = blockIdx.z;
    const int q0 = qt * 128;
    const int m0 = wid * 16;

#pragma unroll
    for (int p = 0; p < 8; p++) {
        int idx = tid + p * 256;
        int r = idx >> 4, c4 = (idx & 15) << 2;
        float4 v = *(const float4*)(g_q +
            ((size_t)((b * S_ + q0 + r) * H_ + h)) * KD + c4);
        uint32_t* dst = (uint32_t*)(sQ + r * 68 + c4);
        dst[0] = f2tf32(0.125f * v.x);
        dst[1] = f2tf32(0.125f * v.y);
        dst[2] = f2tf32(0.125f * v.z);
        dst[3] = f2tf32(0.125f * v.w);
    }
    const float mq0 = g_maskf[b * S_ + q0 + m0 + g];
    const float mq1 = g_maskf[b * S_ + q0 + m0 + g + 8];
    __syncthreads();

    uint32_t Qf[8][4];
    {
        const uint32_t* qb = (const uint32_t*)sQ;
#pragma unroll
        for (int ks = 0; ks < 8; ks++) {
            Qf[ks][0] = qb[(m0 + g) * 68 + ks * 8 + tc];
            Qf[ks][1] = qb[(m0 + g + 8) * 68 + ks * 8 + tc];
            Qf[ks][2] = qb[(m0 + g) * 68 + ks * 8 + tc + 4];
            Qf[ks][3] = qb[(m0 + g + 8) * 68 + ks * 8 + tc + 4];
        }
    }

    float O[8][4];
#pragma unroll
    for (int nt = 0; nt < 8; nt++)
#pragma unroll
        for (int r = 0; r < 4; r++) O[nt][r] = 0.f;
    float m0r = -INFINITY, m1r = -INFINITY, l0 = 0.f, l1 = 0.f;

    const int src0 = (lane & ~3) | (tc >> 1);
    const int src2 = src0 + 2;
    const bool odd = (tc & 1) != 0;

    for (int jt = 0; jt < 16; jt++) {
        const int k0 = jt * 64;
        __syncthreads();
#pragma unroll
        for (int p = 0; p < 4; p++) {
            int idx = tid + p * 256;
            int r = idx >> 4, c4 = (idx & 15) << 2;
            size_t base = ((size_t)((b * S_ + k0 + r) * H_ + h)) * KD + c4;
            float4 kv = *(const float4*)(g_k + base);
            uint32_t* kd = (uint32_t*)(sK + r * 68 + c4);
            kd[0] = f2tf32(kv.x); kd[1] = f2tf32(kv.y);
            kd[2] = f2tf32(kv.z); kd[3] = f2tf32(kv.w);
            float4 vv = *(const float4*)(g_v + base);
            uint32_t* vd = (uint32_t*)(sV + r * 72 + c4);
            vd[0] = f2tf32(vv.x); vd[1] = f2tf32(vv.y);
            vd[2] = f2tf32(vv.z); vd[3] = f2tf32(vv.w);
        }
        if (tid < 64) smk[tid] = g_maskf[b * S_ + k0 + tid];
        __syncthreads();

        float Sf[8][4];
#pragma unroll
        for (int nt = 0; nt < 8; nt++)
#pragma unroll
            for (int r = 0; r < 4; r++) Sf[nt][r] = 0.f;
        const uint32_t* kb = (const uint32_t*)sK;
#pragma unroll
        for (int nt = 0; nt < 8; nt++) {
#pragma unroll
            for (int ks = 0; ks < 8; ks++) {
                uint32_t bfr[2];
                bfr[0] = kb[(nt * 8 + g) * 68 + ks * 8 + tc];
                bfr[1] = kb[(nt * 8 + g) * 68 + ks * 8 + tc + 4];
                mma_tf32(Sf[nt], Qf[ks], bfr);
            }
        }

        float tmax0 = -INFINITY, tmax1 = -INFINITY;
#pragma unroll
        for (int nt = 0; nt < 8; nt++) {
            const float mk0 = smk[nt * 8 + 2 * tc];
            const float mk1 = smk[nt * 8 + 2 * tc + 1];
            Sf[nt][0] += (1.f - mq0 * mk0) * NEGINF;
            Sf[nt][1] += (1.f - mq0 * mk1) * NEGINF;
            Sf[nt][2] += (1.f - mq1 * mk0) * NEGINF;
            Sf[nt][3] += (1.f - mq1 * mk1) * NEGINF;
            tmax0 = fmaxf(tmax0, fmaxf(Sf[nt][0], Sf[nt][1]));
            tmax1 = fmaxf(tmax1, fmaxf(Sf[nt][2], Sf[nt][3]));
        }
        tmax0 = fmaxf(tmax0, __shfl_xor_sync(0xffffffffu, tmax0, 1));
        tmax0 = fmaxf(tmax0, __shfl_xor_sync(0xffffffffu, tmax0, 2));
        tmax1 = fmaxf(tmax1, __shfl_xor_sync(0xffffffffu, tmax1, 1));
        tmax1 = fmaxf(tmax1, __shfl_xor_sync(0xffffffffu, tmax1, 2));

        const float nm0 = fmaxf(m0r, tmax0);
        const float nm1 = fmaxf(m1r, tmax1);
        const float corr0 = __expf(m0r - nm0);
        const float corr1 = __expf(m1r - nm1);
        m0r = nm0; m1r = nm1;

        float rs0 = 0.f, rs1 = 0.f;
#pragma unroll
        for (int nt = 0; nt < 8; nt++) {
            Sf[nt][0] = __expf(Sf[nt][0] - nm0); rs0 += Sf[nt][0];
            Sf[nt][1] = __expf(Sf[nt][1] - nm0); rs0 += Sf[nt][1];
            Sf[nt][2] = __expf(Sf[nt][2] - nm1); rs1 += Sf[nt][2];
            Sf[nt][3] = __expf(Sf[nt][3] - nm1); rs1 += Sf[nt][3];
        }
        rs0 += __shfl_xor_sync(0xffffffffu, rs0, 1);
        rs0 += __shfl_xor_sync(0xffffffffu, rs0, 2);
        rs1 += __shfl_xor_sync(0xffffffffu, rs1, 1);
        rs1 += __shfl_xor_sync(0xffffffffu, rs1, 2);
        l0 = l0 * corr0 + rs0;
        l1 = l1 * corr1 + rs1;

#pragma unroll
        for (int nt = 0; nt < 8; nt++) {
            O[nt][0] *= corr0; O[nt][1] *= corr0;
            O[nt][2] *= corr1; O[nt][3] *= corr1;
        }

        const uint32_t* vb = (const uint32_t*)sV;
#pragma unroll
        for (int ks = 0; ks < 8; ks++) {
            float p00 = __shfl_sync(0xffffffffu, Sf[ks][0], src0);
            float p01 = __shfl_sync(0xffffffffu, Sf[ks][1], src0);
            float p10 = __shfl_sync(0xffffffffu, Sf[ks][2], src0);
            float p11 = __shfl_sync(0xffffffffu, Sf[ks][3], src0);
            float p20 = __shfl_sync(0xffffffffu, Sf[ks][0], src2);
            float p21 = __shfl_sync(0xffffffffu, Sf[ks][1], src2);
            float p30 = __shfl_sync(0xffffffffu, Sf[ks][2], src2);
            float p31 = __shfl_sync(0xffffffffu, Sf[ks][3], src2);
            uint32_t Af[4];
            Af[0] = f2tf32(odd ? p01 : p00);
            Af[1] = f2tf32(odd ? p11 : p10);
            Af[2] = f2tf32(odd ? p21 : p20);
            Af[3] = f2tf32(odd ? p31 : p30);
#pragma unroll
            for (int nt = 0; nt < 8; nt++) {
                uint32_t bfr[2];
                bfr[0] = vb[(ks * 8 + tc) * 72 + nt * 8 + g];
                bfr[1] = vb[(ks * 8 + tc + 4) * 72 + nt * 8 + g];
                mma_tf32(O[nt], Af, bfr);
            }
        }
    }

    // Write ctx directly in AF (tf32 fragment) layout for the Wo GEMM.
    // value(m, kcol): m = b*1024+q0+m0+g (+8), kcol = h*64 + nt*8 + 2tc (+1)
    const float inv0 = 1.f / l0, inv1 = 1.f / l1;
    const int m16 = (b * S_ + q0 + m0) >> 4;
    const int lp = g * 4 + ((2 * tc) & 3);
    const int q2 = ((2 * tc) & 4) >> 1;  // 0 or 2
#pragma unroll
    for (int nt = 0; nt < 8; nt++) {
        uint32_t* base = g_cxf +
            ((size_t)(m16 * 128 + h * 8 + nt) * 32 + lp) * 4 + q2;
        uint2 w0, w1;
        w0.x = f2tf32(O[nt][0] * inv0);  // (m, k)      r bit0=0
        w0.y = f2tf32(O[nt][2] * inv1);  // (m+8, k)    r bit0=1
        w1.x = f2tf32(O[nt][1] * inv0);  // (m, k+1) -> lane+1
        w1.y = f2tf32(O[nt][3] * inv1);  // (m+8, k+1)
        *(uint2*)base = w0;
        *(uint2*)(base + 4) = w1;
    }
}

// ---------------------------------------------------------------------------
extern "C" void kernel_launch(void* const* d_in, const int* in_sizes, int n_in,
                              void* d_out, int out_size)
{
    const float* x  = (const float*)d_in[0];
    const unsigned char* mask = (const unsigned char*)d_in[1];
    const float* Wq = (const float*)d_in[2];
    const float* bq = (const float*)d_in[3];
    const float* Wk = (const float*)d_in[4];
    const float* bk = (const float*)d_in[5];
    const float* Wv = (const float*)d_in[6];
    const float* bv = (const float*)d_in[7];
    const float* Wo = (const float*)d_in[8];
    const float* bo = (const float*)d_in[9];
    float* out = (float*)d_out;

    float *qp, *kp, *vp;
    uint32_t *xfp, *cxfp, *wfp;
    cudaGetSymbolAddress((void**)&qp, g_q);
    cudaGetSymbolAddress((void**)&kp, g_k);
    cudaGetSymbolAddress((void**)&vp, g_v);
    cudaGetSymbolAddress((void**)&xfp, g_xf);
    cudaGetSymbolAddress((void**)&cxfp, g_cxf);
    cudaGetSymbolAddress((void**)&wfp, g_wf);

    const int gemm_smem = 4 * 4096 * sizeof(uint32_t);  // 64KB
    cudaFuncSetAttribute(gemm_frag_kernel,
                         cudaFuncAttributeMaxDynamicSharedMemorySize,
                         gemm_smem);
    const int attn_smem =
        (128 * 68 + 64 * 68 + 64 * 72 + 64) * sizeof(float);
    cudaFuncSetAttribute(attn_mma_kernel,
                         cudaFuncAttributeMaxDynamicSharedMemorySize,
                         attn_smem);

    mask_norm_kernel<<<1, 256>>>(mask);
    xconv_kernel<<<8192, 256>>>(x);
    wconv_kernel<<<dim3(2048, 4), 256>>>(Wq, Wk, Wv, Wo);

    // Fused QKV: z selects (Wq,bq,q) / (Wk,bk,k) / (Wv,bv,v)
    gemm_frag_kernel<<<dim3(8, 64, 3), 256, gemm_smem>>>(
        xfp, wfp, 0, bq, bk, bv, qp, kp, vp);

    attn_mma_kernel<<<dim3(8, H_, B_), 256, attn_smem>>>();

    gemm_frag_kernel<<<dim3(8, 64, 1), 256, gemm_smem>>>(
        cxfp, wfp, 3, bo, bo, bo, out, out, out);
}

// round 17
// speedup vs baseline: 2.8085x; 1.0571x over previous
#include <cuda_runtime.h>
#include <math.h>
#include <stdint.h>

#define B_ 8
#define S_ 1024
#define D_ 1024
#define H_ 16
#define KD 64
#define NEGINF (-1e9f)

// Scratch (allocation-free rule: __device__ globals)
// q/k/v hold tf32 BITS (q pre-scaled by 0.125) written by the QKV GEMM.
static __device__ uint32_t g_qb[B_ * S_ * H_ * KD];
static __device__ uint32_t g_kb[B_ * S_ * H_ * KD];
static __device__ uint32_t g_vb[B_ * S_ * H_ * KD];
static __device__ float g_maskf[B_ * S_];
// Fragment-layout tf32 buffers
static __device__ uint32_t g_xf[B_ * S_ * D_];        // x,  AF layout
static __device__ uint32_t g_cxf[B_ * S_ * H_ * KD];  // ctx, AF layout
static __device__ uint32_t g_wf[4 * D_ * H_ * KD];    // Wq,Wk,Wv,Wo WF layout

// AF layout: [m16 (M/16)][ks (K/8)][lane 32][r 4]
//   lane = (m&7)*4 + (k&3);  r = ((k&4)>>1) | ((m&8)>>3)
// WF layout: [n8 (N/8)][ks (K/8)][lane 32][q 2]
//   lane = (n&7)*4 + (k&3);  q = (k&4)>>2

// ---------------------------------------------------------------------------
static __device__ __forceinline__ uint32_t f2tf32(float f) {
    uint32_t u;
    asm("cvt.rna.tf32.f32 %0, %1;" : "=r"(u) : "f"(f));
    return u;
}

static __device__ __forceinline__ void mma_tf32(float* d,
                                                const uint32_t* a,
                                                const uint32_t* b) {
    asm volatile(
        "mma.sync.aligned.m16n8k8.row.col.f32.tf32.tf32.f32 "
        "{%0,%1,%2,%3}, {%4,%5,%6,%7}, {%8,%9}, {%0,%1,%2,%3};"
        : "+f"(d[0]), "+f"(d[1]), "+f"(d[2]), "+f"(d[3])
        : "r"(a[0]), "r"(a[1]), "r"(a[2]), "r"(a[3]),
          "r"(b[0]), "r"(b[1]));
}

static __device__ __forceinline__ uint32_t smem_u32(const void* p) {
    uint32_t a;
    asm("{ .reg .u64 t; cvta.to.shared.u64 t, %1; cvt.u32.u64 %0, t; }"
        : "=r"(a) : "l"(p));
    return a;
}

static __device__ __forceinline__ void cp_async16(uint32_t dst,
                                                  const void* src) {
    asm volatile("cp.async.cg.shared.global [%0], [%1], 16;"
                 :: "r"(dst), "l"(src));
}
#define CP_COMMIT() asm volatile("cp.async.commit_group;" ::: "memory")
#define CP_WAIT0()  asm volatile("cp.async.wait_group 0;" ::: "memory")

// ---------------------------------------------------------------------------
// Mask dtype sniffing + normalization into g_maskf.
// ---------------------------------------------------------------------------
__global__ void mask_norm_kernel(const unsigned char* __restrict__ m)
{
    __shared__ int mode;
    if (threadIdx.x == 0) {
        int any_ge2 = 0, any_off = 0;
        for (int i = 0; i < 512; i++) {
            unsigned char v = m[i];
            if (v >= 2) any_ge2 = 1;
            if ((i & 3) && v) any_off = 1;
        }
        mode = (any_ge2 || !any_off) ? 1 : 0;
    }
    __syncthreads();
    const int n = B_ * S_;
    if (mode) {
        const unsigned int* w = (const unsigned int*)m;
        for (int i = threadIdx.x; i < n; i += blockDim.x)
            g_maskf[i] = w[i] ? 1.f : 0.f;
    } else {
        for (int i = threadIdx.x; i < n; i += blockDim.x)
            g_maskf[i] = m[i] ? 1.f : 0.f;
    }
}

// ---------------------------------------------------------------------------
// x [8192][1024] fp32 -> g_xf AF layout (tf32). One uint4 per thread.
// ---------------------------------------------------------------------------
__global__ __launch_bounds__(256)
void xconv_kernel(const float* __restrict__ x)
{
    const int idx = blockIdx.x * 256 + threadIdx.x;
    const int lane = idx & 31;
    const int ks = (idx >> 5) & 127;
    const int m16 = idx >> 12;
    const int m = m16 * 16 + (lane >> 2);
    const int k = ks * 8 + (lane & 3);
    const float* p0 = x + (size_t)m * 1024 + k;
    uint4 o;
    o.x = f2tf32(p0[0]);
    o.y = f2tf32(p0[8 * 1024]);
    o.z = f2tf32(p0[4]);
    o.w = f2tf32(p0[8 * 1024 + 4]);
    ((uint4*)g_xf)[idx] = o;
}

// ---------------------------------------------------------------------------
// W [1024][1024] fp32 (4 of them) -> g_wf WF layout (tf32). uint2 per thread.
// ---------------------------------------------------------------------------
__global__ __launch_bounds__(256)
void wconv_kernel(const float* __restrict__ W0,
                  const float* __restrict__ W1,
                  const float* __restrict__ W2,
                  const float* __restrict__ W3)
{
    const int w = blockIdx.y;
    const float* W = (w == 0) ? W0 : (w == 1) ? W1 : (w == 2) ? W2 : W3;
    const int idx = blockIdx.x * 256 + threadIdx.x;
    const int lane = idx & 31;
    const int ks = (idx >> 5) & 127;
    const int n8 = idx >> 12;
    const int k = ks * 8 + (lane & 3);
    const int n = n8 * 8 + (lane >> 2);
    uint2 o;
    o.x = f2tf32(W[(size_t)k * 1024 + n]);
    o.y = f2tf32(W[(size_t)(k + 4) * 1024 + n]);
    ((uint2*)(g_wf + (size_t)w * 1024 * 1024))[idx] = o;
}

// ---------------------------------------------------------------------------
// tf32 mma.sync GEMM, frag-ready operands, cp.async double-buffered.
// qkv_mode=1: outputs are tf32 BITS (uint32), z==0 scaled by 0.125 (Q).
// qkv_mode=0: outputs fp32 (final projection -> d_out).
// ---------------------------------------------------------------------------
__global__ __launch_bounds__(256, 2)
void gemm_frag_kernel(const uint32_t* __restrict__ AF,
                      const uint32_t* __restrict__ WFbase, int wsel,
                      const float* __restrict__ b0p,
                      const float* __restrict__ b1p,
                      const float* __restrict__ b2p,
                      void* __restrict__ C0,
                      void* __restrict__ C1,
                      void* __restrict__ C2,
                      int qkv_mode)
{
    extern __shared__ uint32_t smem[];

    const int z = blockIdx.z;
    const uint32_t* WF = WFbase + (size_t)(wsel + z) * 1024 * 1024;
    const float* bias = (z == 0) ? b0p : (z == 1) ? b1p : b2p;
    void* C            = (z == 0) ? C0 : (z == 1) ? C1 : C2;

    const int tid = threadIdx.x;
    const int wid = tid >> 5, lane = tid & 31;
    const int bm = blockIdx.y, bn = blockIdx.x;

    const int gr = lane >> 2;
    const int tc = lane & 3;

    float acc[4][4][4];
#pragma unroll
    for (int mt = 0; mt < 4; mt++)
#pragma unroll
        for (int nt = 0; nt < 4; nt++)
#pragma unroll
            for (int r = 0; r < 4; r++) acc[mt][nt][r] = 0.f;

    const uint32_t sA_u = smem_u32(smem);
    const uint32_t sB_u = sA_u + 32768;

    const char* AFb = (const char*)AF;
    const char* WFb = (const char*)WF;

#pragma unroll
    for (int p = 0; p < 4; p++) {
        const int off = tid * 16 + p * 4096;
        const int m16l = off >> 11, ainner = off & 2047;
        cp_async16(sA_u + off,
                   AFb + ((size_t)(bm * 8 + m16l) * 128 + 0) * 512 + ainner);
        const int n8l = off >> 10, binner = off & 1023;
        cp_async16(sB_u + off,
                   WFb + ((size_t)(bn * 16 + n8l) * 128 + 0) * 256 + binner);
    }
    CP_COMMIT();

    for (int ic = 0; ic < 32; ic++) {
        const int buf = ic & 1;
        CP_WAIT0();
        __syncthreads();

        if (ic < 31) {
            const int ks0 = (ic + 1) * 4;
            const int nbuf = (buf ^ 1) * 16384;
#pragma unroll
            for (int p = 0; p < 4; p++) {
                const int off = tid * 16 + p * 4096;
                const int m16l = off >> 11, ainner = off & 2047;
                cp_async16(sA_u + nbuf + off,
                           AFb + ((size_t)(bm * 8 + m16l) * 128 + ks0) * 512 +
                               ainner);
                const int n8l = off >> 10, binner = off & 1023;
                cp_async16(sB_u + nbuf + off,
                           WFb + ((size_t)(bn * 16 + n8l) * 128 + ks0) * 256 +
                               binner);
            }
            CP_COMMIT();
        }

        const uint32_t* sAb = smem + buf * 4096;
        const uint32_t* sBb = smem + 8192 + buf * 4096;
        const int am = (wid & 1) * 4;
        const int bn8 = (wid >> 1) * 4;
#pragma unroll
        for (int ks = 0; ks < 4; ks++) {
            uint4 af[4];
            uint2 bf[4];
#pragma unroll
            for (int mt = 0; mt < 4; mt++)
                af[mt] = *(const uint4*)(sAb +
                    (((am + mt) * 4 + ks) * 32 + lane) * 4);
#pragma unroll
            for (int nt = 0; nt < 4; nt++)
                bf[nt] = *(const uint2*)(sBb +
                    (((bn8 + nt) * 4 + ks) * 32 + lane) * 2);
#pragma unroll
            for (int mt = 0; mt < 4; mt++)
#pragma unroll
                for (int nt = 0; nt < 4; nt++)
                    mma_tf32(acc[mt][nt], (const uint32_t*)&af[mt],
                             (const uint32_t*)&bf[nt]);
        }
    }

    const int warp_m = (wid & 1) * 64;
    const int warp_n = (wid >> 1) * 32;
    const float scale = (qkv_mode && z == 0) ? 0.125f : 1.f;
#pragma unroll
    for (int mt = 0; mt < 4; mt++) {
        const int row0 = bm * 128 + warp_m + mt * 16 + gr;
#pragma unroll
        for (int nt = 0; nt < 4; nt++) {
            const int col = bn * 128 + warp_n + nt * 8 + 2 * tc;
            const float bb0 = bias[col], bb1 = bias[col + 1];
            const float v00 = acc[mt][nt][0] + bb0;
            const float v01 = acc[mt][nt][1] + bb1;
            const float v10 = acc[mt][nt][2] + bb0;
            const float v11 = acc[mt][nt][3] + bb1;
            if (qkv_mode) {
                uint32_t* c0 = (uint32_t*)C + (size_t)row0 * 1024 + col;
                uint32_t* c1 = (uint32_t*)C + (size_t)(row0 + 8) * 1024 + col;
                c0[0] = f2tf32(scale * v00);
                c0[1] = f2tf32(scale * v01);
                c1[0] = f2tf32(scale * v10);
                c1[1] = f2tf32(scale * v11);
            } else {
                float* c0 = (float*)C + (size_t)row0 * 1024 + col;
                float* c1 = (float*)C + (size_t)(row0 + 8) * 1024 + col;
                c0[0] = v00; c0[1] = v01;
                c1[0] = v10; c1[1] = v11;
            }
        }
    }
}

// ---------------------------------------------------------------------------
// tf32 mma.sync flash attention. q/k/v are tf32 bits (Q pre-scaled 0.125).
// cp.async double-buffered K/V tiles; mask preloaded to SMEM once.
// SMEM words: sQ 128*68 | sK 2*64*68 | sV 2*64*72 | smask 1024  (110.6KB)
// ---------------------------------------------------------------------------
__global__ __launch_bounds__(256, 2)
void attn_mma_kernel()
{
    extern __shared__ uint32_t sm[];
    uint32_t* sQ    = sm;                    // 8704
    uint32_t* sK    = sQ + 128 * 68;         // 2 * 4352
    uint32_t* sV    = sK + 2 * 64 * 68;      // 2 * 4608
    float*    smask = (float*)(sV + 2 * 64 * 72);  // 1024

    const int tid = threadIdx.x;
    const int wid = tid >> 5, lane = tid & 31;
    const int g = lane >> 2, tc = lane & 3;
    const int qt = blockIdx.x, h = blockIdx.y, b = blockIdx.z;
    const int q0 = qt * 128;
    const int m0 = wid * 16;

    const uint32_t sK_u = smem_u32(sK);
    const uint32_t sV_u = smem_u32(sV);

    // Stage Q bits (already scaled+tf32) and the full mask row
#pragma unroll
    for (int p = 0; p < 8; p++) {
        int idx = tid + p * 256;
        int r = idx >> 4, c4 = (idx & 15) << 2;
        *(uint4*)(sQ + r * 68 + c4) = *(const uint4*)(g_qb +
            ((size_t)((b * S_ + q0 + r) * H_ + h)) * KD + c4);
    }
#pragma unroll
    for (int p = 0; p < 4; p++)
        smask[tid + p * 256] = g_maskf[b * S_ + tid + p * 256];

    // Prologue: cp.async K/V tile 0 into buffer 0
#pragma unroll
    for (int p = 0; p < 4; p++) {
        int idx = tid + p * 256;
        int r = idx >> 4, c4 = (idx & 15) << 2;
        size_t base = ((size_t)((b * S_ + r) * H_ + h)) * KD + c4;
        cp_async16(sK_u + (r * 68 + c4) * 4, g_kb + base);
        cp_async16(sV_u + (r * 72 + c4) * 4, g_vb + base);
    }
    CP_COMMIT();
    __syncthreads();

    const float mq0 = smask[q0 + m0 + g];
    const float mq1 = smask[q0 + m0 + g + 8];

    uint32_t Qf[8][4];
#pragma unroll
    for (int ks = 0; ks < 8; ks++) {
        Qf[ks][0] = sQ[(m0 + g) * 68 + ks * 8 + tc];
        Qf[ks][1] = sQ[(m0 + g + 8) * 68 + ks * 8 + tc];
        Qf[ks][2] = sQ[(m0 + g) * 68 + ks * 8 + tc + 4];
        Qf[ks][3] = sQ[(m0 + g + 8) * 68 + ks * 8 + tc + 4];
    }

    float O[8][4];
#pragma unroll
    for (int nt = 0; nt < 8; nt++)
#pragma unroll
        for (int r = 0; r < 4; r++) O[nt][r] = 0.f;
    float m0r = -INFINITY, m1r = -INFINITY, l0 = 0.f, l1 = 0.f;

    const int src0 = (lane & ~3) | (tc >> 1);
    const int src2 = src0 + 2;
    const bool odd = (tc & 1) != 0;

    for (int jt = 0; jt < 16; jt++) {
        const int buf = jt & 1;
        CP_WAIT0();
        __syncthreads();  // tile jt landed; all warps done with buf^1

        if (jt < 15) {
            const int k0n = (jt + 1) * 64;
            const int nb = buf ^ 1;
#pragma unroll
            for (int p = 0; p < 4; p++) {
                int idx = tid + p * 256;
                int r = idx >> 4, c4 = (idx & 15) << 2;
                size_t base =
                    ((size_t)((b * S_ + k0n + r) * H_ + h)) * KD + c4;
                cp_async16(sK_u + (nb * 4352 + r * 68 + c4) * 4, g_kb + base);
                cp_async16(sV_u + (nb * 4608 + r * 72 + c4) * 4, g_vb + base);
            }
            CP_COMMIT();
        }

        const uint32_t* kb = sK + buf * 4352;
        const uint32_t* vb = sV + buf * 4608;
        const int k0 = jt * 64;

        float Sf[8][4];
#pragma unroll
        for (int nt = 0; nt < 8; nt++)
#pragma unroll
            for (int r = 0; r < 4; r++) Sf[nt][r] = 0.f;
#pragma unroll
        for (int nt = 0; nt < 8; nt++) {
#pragma unroll
            for (int ks = 0; ks < 8; ks++) {
                uint32_t bfr[2];
                bfr[0] = kb[(nt * 8 + g) * 68 + ks * 8 + tc];
                bfr[1] = kb[(nt * 8 + g) * 68 + ks * 8 + tc + 4];
                mma_tf32(Sf[nt], Qf[ks], bfr);
            }
        }

        float tmax0 = -INFINITY, tmax1 = -INFINITY;
#pragma unroll
        for (int nt = 0; nt < 8; nt++) {
            const float mk0 = smask[k0 + nt * 8 + 2 * tc];
            const float mk1 = smask[k0 + nt * 8 + 2 * tc + 1];
            Sf[nt][0] += (1.f - mq0 * mk0) * NEGINF;
            Sf[nt][1] += (1.f - mq0 * mk1) * NEGINF;
            Sf[nt][2] += (1.f - mq1 * mk0) * NEGINF;
            Sf[nt][3] += (1.f - mq1 * mk1) * NEGINF;
            tmax0 = fmaxf(tmax0, fmaxf(Sf[nt][0], Sf[nt][1]));
            tmax1 = fmaxf(tmax1, fmaxf(Sf[nt][2], Sf[nt][3]));
        }
        tmax0 = fmaxf(tmax0, __shfl_xor_sync(0xffffffffu, tmax0, 1));
        tmax0 = fmaxf(tmax0, __shfl_xor_sync(0xffffffffu, tmax0, 2));
        tmax1 = fmaxf(tmax1, __shfl_xor_sync(0xffffffffu, tmax1, 1));
        tmax1 = fmaxf(tmax1, __shfl_xor_sync(0xffffffffu, tmax1, 2));

        const float nm0 = fmaxf(m0r, tmax0);
        const float nm1 = fmaxf(m1r, tmax1);
        const float corr0 = __expf(m0r - nm0);
        const float corr1 = __expf(m1r - nm1);
        m0r = nm0; m1r = nm1;

        float rs0 = 0.f, rs1 = 0.f;
#pragma unroll
        for (int nt = 0; nt < 8; nt++) {
            Sf[nt][0] = __expf(Sf[nt][0] - nm0); rs0 += Sf[nt][0];
            Sf[nt][1] = __expf(Sf[nt][1] - nm0); rs0 += Sf[nt][1];
            Sf[nt][2] = __expf(Sf[nt][2] - nm1); rs1 += Sf[nt][2];
            Sf[nt][3] = __expf(Sf[nt][3] - nm1); rs1 += Sf[nt][3];
        }
        rs0 += __shfl_xor_sync(0xffffffffu, rs0, 1);
        rs0 += __shfl_xor_sync(0xffffffffu, rs0, 2);
        rs1 += __shfl_xor_sync(0xffffffffu, rs1, 1);
        rs1 += __shfl_xor_sync(0xffffffffu, rs1, 2);
        l0 = l0 * corr0 + rs0;
        l1 = l1 * corr1 + rs1;

#pragma unroll
        for (int nt = 0; nt < 8; nt++) {
            O[nt][0] *= corr0; O[nt][1] *= corr0;
            O[nt][2] *= corr1; O[nt][3] *= corr1;
        }

#pragma unroll
        for (int ks = 0; ks < 8; ks++) {
            float p00 = __shfl_sync(0xffffffffu, Sf[ks][0], src0);
            float p01 = __shfl_sync(0xffffffffu, Sf[ks][1], src0);
            float p10 = __shfl_sync(0xffffffffu, Sf[ks][2], src0);
            float p11 = __shfl_sync(0xffffffffu, Sf[ks][3], src0);
            float p20 = __shfl_sync(0xffffffffu, Sf[ks][0], src2);
            float p21 = __shfl_sync(0xffffffffu, Sf[ks][1], src2);
            float p30 = __shfl_sync(0xffffffffu, Sf[ks][2], src2);
            float p31 = __shfl_sync(0xffffffffu, Sf[ks][3], src2);
            uint32_t Af[4];
            Af[0] = f2tf32(odd ? p01 : p00);
            Af[1] = f2tf32(odd ? p11 : p10);
            Af[2] = f2tf32(odd ? p21 : p20);
            Af[3] = f2tf32(odd ? p31 : p30);
#pragma unroll
            for (int nt = 0; nt < 8; nt++) {
                uint32_t bfr[2];
                bfr[0] = vb[(ks * 8 + tc) * 72 + nt * 8 + g];
                bfr[1] = vb[(ks * 8 + tc + 4) * 72 + nt * 8 + g];
                mma_tf32(O[nt], Af, bfr);
            }
        }
    }

    // Write ctx directly in AF (tf32 fragment) layout for the Wo GEMM.
    const float inv0 = 1.f / l0, inv1 = 1.f / l1;
    const int m16 = (b * S_ + q0 + m0) >> 4;
    const int lp = g * 4 + ((2 * tc) & 3);
    const int q2 = ((2 * tc) & 4) >> 1;
#pragma unroll
    for (int nt = 0; nt < 8; nt++) {
        uint32_t* base = g_cxf +
            ((size_t)(m16 * 128 + h * 8 + nt) * 32 + lp) * 4 + q2;
        uint2 w0, w1;
        w0.x = f2tf32(O[nt][0] * inv0);
        w0.y = f2tf32(O[nt][2] * inv1);
        w1.x = f2tf32(O[nt][1] * inv0);
        w1.y = f2tf32(O[nt][3] * inv1);
        *(uint2*)base = w0;
        *(uint2*)(base + 4) = w1;
    }
}

// ---------------------------------------------------------------------------
extern "C" void kernel_launch(void* const* d_in, const int* in_sizes, int n_in,
                              void* d_out, int out_size)
{
    const float* x  = (const float*)d_in[0];
    const unsigned char* mask = (const unsigned char*)d_in[1];
    const float* Wq = (const float*)d_in[2];
    const float* bq = (const float*)d_in[3];
    const float* Wk = (const float*)d_in[4];
    const float* bk = (const float*)d_in[5];
    const float* Wv = (const float*)d_in[6];
    const float* bv = (const float*)d_in[7];
    const float* Wo = (const float*)d_in[8];
    const float* bo = (const float*)d_in[9];
    float* out = (float*)d_out;

    uint32_t *qp, *kp, *vp, *xfp, *cxfp, *wfp;
    cudaGetSymbolAddress((void**)&qp, g_qb);
    cudaGetSymbolAddress((void**)&kp, g_kb);
    cudaGetSymbolAddress((void**)&vp, g_vb);
    cudaGetSymbolAddress((void**)&xfp, g_xf);
    cudaGetSymbolAddress((void**)&cxfp, g_cxf);
    cudaGetSymbolAddress((void**)&wfp, g_wf);

    const int gemm_smem = 4 * 4096 * sizeof(uint32_t);  // 64KB
    cudaFuncSetAttribute(gemm_frag_kernel,
                         cudaFuncAttributeMaxDynamicSharedMemorySize,
                         gemm_smem);
    const int attn_smem =
        (128 * 68 + 2 * 64 * 68 + 2 * 64 * 72 + 1024) * sizeof(uint32_t);
    cudaFuncSetAttribute(attn_mma_kernel,
                         cudaFuncAttributeMaxDynamicSharedMemorySize,
                         attn_smem);

    mask_norm_kernel<<<1, 256>>>(mask);
    xconv_kernel<<<8192, 256>>>(x);
    wconv_kernel<<<dim3(2048, 4), 256>>>(Wq, Wk, Wv, Wo);

    // Fused QKV: z selects (Wq,bq,q) / (Wk,bk,k) / (Wv,bv,v); tf32-bit out
    gemm_frag_kernel<<<dim3(8, 64, 3), 256, gemm_smem>>>(
        xfp, wfp, 0, bq, bk, bv, qp, kp, vp, 1);

    attn_mma_kernel<<<dim3(8, H_, B_), 256, attn_smem>>>();

    gemm_frag_kernel<<<dim3(8, 64, 1), 256, gemm_smem>>>(
        cxfp, wfp, 3, bo, bo, bo, out, out, out, 0);
}